// round 5
// baseline (speedup 1.0000x reference)
#include <cuda_runtime.h>

#define TPB 256
#define CPB 256          // cells per block
#define MAX_GRID 16384

// SoA per-block partials: [k * grid + bid], k in {nobj_count, reg, conf, noobj, cls}
__device__ float g_partials[5 * MAX_GRID];
__device__ unsigned int g_counter = 0;   // atomicInc wraps back to 0 -> replay-safe

__device__ __forceinline__ float iou_pred_vs_tgt(
    float px, float py, float pw, float ph,
    float tx1, float ty1, float tx2, float ty2, float tarea)
{
    const float invS = 1.0f / 14.0f;
    float cx = px * invS, cy = py * invS;
    float x1 = cx - 0.5f * pw, y1 = cy - 0.5f * ph;
    float x2 = cx + 0.5f * pw, y2 = cy + 0.5f * ph;
    float lx = fmaxf(x1, tx1), ly = fmaxf(y1, ty1);
    float rx = fminf(x2, tx2), ry = fminf(y2, ty2);
    float wx = fmaxf(rx - lx, 0.0f), wy = fmaxf(ry - ly, 0.0f);
    float inter = wx * wy;
    float a1 = (x2 - x1) * (y2 - y1);
    return inter / (a1 + tarea - inter);
}

__global__ void __launch_bounds__(TPB, 6)
yolo_fused_kernel(const float* __restrict__ pred,
                  const float* __restrict__ tbox,
                  const float* __restrict__ tcls,
                  const void* __restrict__ objmap,
                  int n_cells, float n_batch, float* __restrict__ out)
{
    __shared__ float s_box[CPB * 12];         // float2-aligned stride
    __shared__ float s_obj[CPB];
    __shared__ float s_red[5 * (TPB / 32)];
    __shared__ double s_dred[TPB / 32];
    __shared__ double s_tot[5];
    __shared__ int s_last;

    const int tid  = threadIdx.x;
    const int lane = tid & 31;
    const int warp = tid >> 5;
    const int bid  = blockIdx.x;
    const int grid = gridDim.x;
    const int cellbase = bid * CPB;
    int cib = n_cells - cellbase;
    if (cib > CPB) cib = CPB;

    // ---- dtype detection: every block scans the SAME first 1KB (L2-broadcast) ----
    unsigned int w = ((const unsigned int*)objmap)[tid];
    int isf = __syncthreads_or(w == 0x3F800000u);
    int big = __syncthreads_or((w > 1u) && (w != 0x3F800000u));
    const int flag = isf ? 2 : (big ? 0 : 1);   // 2=float32, 0=bool bytes, 1=int32

    // ---- load object map for this block's cells ----
    if (tid < cib) {
        int idx = cellbase + tid;
        float o;
        if (flag == 2)      o = ((const float*)objmap)[idx];
        else if (flag == 1) o = (((const int*)objmap)[idx] != 0) ? 1.0f : 0.0f;
        else                o = ((const unsigned char*)objmap)[idx] ? 1.0f : 0.0f;
        s_obj[tid] = o;
    }
    __syncthreads();

    // ---- Phase A: strided float2 stream; incremental (cell, r) decode ----
    // i = tid + k*256 ; 256 = 17*15 + 1  =>  cell += 17, r += 1 (wrap at 15)
    float acc_noobj = 0.0f, acc_cls = 0.0f;
    const float2* pred2 = reinterpret_cast<const float2*>(pred + (size_t)cellbase * 30);
    const float2* tcls2 = reinterpret_cast<const float2*>(tcls + (size_t)cellbase * 20);

    {
        int cell = tid / 15;
        int r = tid - cell * 15;
        if (cib == CPB) {
            #pragma unroll
            for (int k = 0; k < 15; k++) {
                float2 v = pred2[tid + k * TPB];
                float obj = s_obj[cell];
                if (r < 5) {
                    *reinterpret_cast<float2*>(&s_box[cell * 12 + 2 * r]) = v;
                    acc_noobj += (1.0f - obj) * (v.x * v.x + v.y * v.y);
                } else {
                    float2 t = tcls2[cell * 10 + (r - 5)];
                    float dx = v.x - t.x, dy = v.y - t.y;
                    acc_cls += obj * (dx * dx + dy * dy);
                }
                cell += 17;
                if (++r == 15) { r = 0; ++cell; }
            }
        } else {
            for (int i = tid; i < cib * 15; i += TPB) {
                float2 v = pred2[i];
                float obj = s_obj[cell];
                if (r < 5) {
                    *reinterpret_cast<float2*>(&s_box[cell * 12 + 2 * r]) = v;
                    acc_noobj += (1.0f - obj) * (v.x * v.x + v.y * v.y);
                } else {
                    float2 t = tcls2[cell * 10 + (r - 5)];
                    float dx = v.x - t.x, dy = v.y - t.y;
                    acc_cls += obj * (dx * dx + dy * dy);
                }
                cell += 17;
                if (++r == 15) { r = 0; ++cell; }
            }
        }
    }
    __syncthreads();

    // ---- Phase B: per-cell IoU/reg/conf from SMEM ----
    float acc_reg = 0.0f, acc_conf = 0.0f, acc_nobjcnt = 0.0f;
    if (tid < cib) {
        float obj = s_obj[tid];
        acc_nobjcnt = obj;
        if (obj > 0.0f) {
            const float invS = 1.0f / 14.0f;
            float4 tb = reinterpret_cast<const float4*>(tbox)[cellbase + tid];
            float tcx = tb.x * invS, tcy = tb.y * invS;
            float tx1 = tcx - 0.5f * tb.z, ty1 = tcy - 0.5f * tb.w;
            float tx2 = tcx + 0.5f * tb.z, ty2 = tcy + 0.5f * tb.w;
            float tarea = (tx2 - tx1) * (ty2 - ty1);

            const float* bb = &s_box[tid * 12];
            float b1x = bb[0], b1y = bb[1], b1w = bb[2], b1h = bb[3], b1c = bb[4];
            float b2x = bb[5], b2y = bb[6], b2w = bb[7], b2h = bb[8], b2c = bb[9];

            float iou1 = iou_pred_vs_tgt(b1x, b1y, b1w, b1h, tx1, ty1, tx2, ty2, tarea);
            float iou2 = iou_pred_vs_tgt(b2x, b2y, b2w, b2h, tx1, ty1, tx2, ty2, tarea);

            bool take1 = (iou1 >= iou2);
            float bx = take1 ? b1x : b2x;
            float by = take1 ? b1y : b2y;
            float bw = take1 ? b1w : b2w;
            float bh = take1 ? b1h : b2h;
            float bc = take1 ? b1c : b2c;
            float biou = take1 ? iou1 : iou2;

            float dx = bx - tb.x;
            float dy = by - tb.y;
            float dw = sqrtf(bw) - sqrtf(tb.z);
            float dh = sqrtf(bh) - sqrtf(tb.w);
            acc_reg = dx * dx + dy * dy + dw * dw + dh * dh;

            float dc = bc - biou;
            acc_conf = dc * dc;
        }
    }

    // ---- Block reduction of 5 accumulators -> SoA partials ----
    float vals[5] = {acc_nobjcnt, acc_reg, acc_conf, acc_noobj, acc_cls};
    #pragma unroll
    for (int k = 0; k < 5; k++) {
        float v = vals[k];
        #pragma unroll
        for (int off = 16; off > 0; off >>= 1)
            v += __shfl_down_sync(0xffffffffu, v, off);
        if (lane == 0) s_red[k * (TPB / 32) + warp] = v;
    }
    __syncthreads();
    if (tid < 5) {
        float v = 0.0f;
        #pragma unroll
        for (int w2 = 0; w2 < TPB / 32; w2++)
            v += s_red[tid * (TPB / 32) + w2];
        g_partials[tid * grid + bid] = v;
    }

    // ---- Last-block finalize ----
    if (tid == 0) {
        __threadfence();
        unsigned int old = atomicInc(&g_counter, (unsigned int)(grid - 1));
        s_last = (old == (unsigned int)(grid - 1)) ? 1 : 0;
    }
    __syncthreads();
    if (!s_last) return;

    volatile float* gp = g_partials;
    double acc[5] = {0.0, 0.0, 0.0, 0.0, 0.0};
    for (int i = tid; i < grid; i += TPB) {
        #pragma unroll
        for (int k = 0; k < 5; k++)
            acc[k] += (double)gp[k * grid + i];
    }
    #pragma unroll
    for (int k = 0; k < 5; k++) {
        double v = acc[k];
        #pragma unroll
        for (int off = 16; off > 0; off >>= 1)
            v += __shfl_down_sync(0xffffffffu, v, off);
        if (lane == 0) s_dred[warp] = v;
        __syncthreads();
        if (tid == 0) {
            double t = 0.0;
            #pragma unroll
            for (int w2 = 0; w2 < TPB / 32; w2++) t += s_dred[w2];
            s_tot[k] = t;
        }
        __syncthreads();
    }

    if (tid == 0) {
        double n_obj   = s_tot[0];
        double n_noobj = (double)n_cells - n_obj;
        double reg_loss   = 5.0 * s_tot[1] / n_obj;
        double conf_loss  = s_tot[2] / n_obj;
        double noobj_loss = 0.5 * s_tot[3] / n_noobj;
        double cls_loss   = s_tot[4] / (double)n_batch;
        double total = reg_loss + conf_loss + noobj_loss + cls_loss;
        out[0] = (float)total;
        out[1] = (float)reg_loss;
        out[2] = (float)conf_loss;
        out[3] = (float)noobj_loss;
        out[4] = (float)cls_loss;
    }
}

extern "C" void kernel_launch(void* const* d_in, const int* in_sizes, int n_in,
                              void* d_out, int out_size)
{
    const float* pred = (const float*)d_in[0];
    const float* tbox = (const float*)d_in[1];
    const float* tcls = (const float*)d_in[2];
    const void*  objmap = d_in[3];
    float* out = (float*)d_out;

    const int n_cells = in_sizes[3];                  // N * S * S
    const int n_batch = in_sizes[0] / (14 * 14 * 30);
    int grid = (n_cells + CPB - 1) / CPB;
    if (grid > MAX_GRID) grid = MAX_GRID;             // not reachable at this shape

    yolo_fused_kernel<<<grid, TPB>>>(pred, tbox, tcls, objmap,
                                     n_cells, (float)n_batch, out);
}

// round 6
// speedup vs baseline: 1.1147x; 1.1147x over previous
#include <cuda_runtime.h>

#define TPB 256
#define CPB 256          // cells per block
#define MAX_GRID 16384

// SoA per-block partials: [k * grid + bid], k in {nobj_count, reg, conf, noobj, cls}
__device__ float g_partials[5 * MAX_GRID];
__device__ unsigned int g_counter = 0;   // atomicInc wraps back to 0 -> replay-safe

__device__ __forceinline__ float iou_pred_vs_tgt(
    float px, float py, float pw, float ph,
    float tx1, float ty1, float tx2, float ty2, float tarea)
{
    const float invS = 1.0f / 14.0f;
    float cx = px * invS, cy = py * invS;
    float x1 = cx - 0.5f * pw, y1 = cy - 0.5f * ph;
    float x2 = cx + 0.5f * pw, y2 = cy + 0.5f * ph;
    float lx = fmaxf(x1, tx1), ly = fmaxf(y1, ty1);
    float rx = fminf(x2, tx2), ry = fminf(y2, ty2);
    float wx = fmaxf(rx - lx, 0.0f), wy = fmaxf(ry - ly, 0.0f);
    float inter = wx * wy;
    float a1 = (x2 - x1) * (y2 - y1);
    return inter / (a1 + tarea - inter);
}

__global__ void __launch_bounds__(TPB, 6)
yolo_fused_kernel(const float* __restrict__ pred,
                  const float* __restrict__ tbox,
                  const float* __restrict__ tcls,
                  const void* __restrict__ objmap,
                  int n_cells, float n_batch, float* __restrict__ out)
{
    __shared__ float s_pred[CPB * 30];        // 30 KB, mirrors gmem layout
    __shared__ float s_obj[CPB];
    __shared__ float s_red[5 * (TPB / 32)];
    __shared__ double s_dred[TPB / 32];
    __shared__ double s_tot[5];
    __shared__ int s_last;

    const int tid  = threadIdx.x;
    const int lane = tid & 31;
    const int warp = tid >> 5;
    const int bid  = blockIdx.x;
    const int grid = gridDim.x;
    const int cellbase = bid * CPB;
    int cib = n_cells - cellbase;
    if (cib > CPB) cib = CPB;

    // ---- dtype detection: every block scans the SAME first 1KB (L2-broadcast) ----
    unsigned int wdet = ((const unsigned int*)objmap)[tid];
    int isf = __syncthreads_or(wdet == 0x3F800000u);
    int big = __syncthreads_or((wdet > 1u) && (wdet != 0x3F800000u));
    const int flag = isf ? 2 : (big ? 0 : 1);   // 2=float32, 0=bool bytes, 1=int32

    // ---- load object map for this block's cells ----
    if (tid < cib) {
        int idx = cellbase + tid;
        float o;
        if (flag == 2)      o = ((const float*)objmap)[idx];
        else if (flag == 1) o = (((const int*)objmap)[idx] != 0) ? 1.0f : 0.0f;
        else                o = ((const unsigned char*)objmap)[idx] ? 1.0f : 0.0f;
        s_obj[tid] = o;
    }

    // ---- Phase A1: stage pred tile to SMEM (pure float4 copy, MLP=8) ----
    if (cib == CPB) {
        const float4* pred4 = reinterpret_cast<const float4*>(pred + (size_t)cellbase * 30);
        float4* s_pred4 = reinterpret_cast<float4*>(s_pred);
        #pragma unroll
        for (int k = 0; k < 8; k++) {
            int i = tid + k * TPB;
            if (i < (CPB * 30) / 4) s_pred4[i] = pred4[i];
        }
    } else {
        const float* predb = pred + (size_t)cellbase * 30;
        for (int i = tid; i < cib * 30; i += TPB) s_pred[i] = predb[i];
    }

    // ---- tbox prefetch (independent of SMEM; hides behind the barrier) ----
    float4 tb = make_float4(0.f, 0.f, 0.f, 0.f);
    if (tid < cib) tb = reinterpret_cast<const float4*>(tbox)[cellbase + tid];

    __syncthreads();

    // ---- Phase A2: cls loop (branch-free; tcls LDG perfectly linear/coalesced) ----
    float acc_cls = 0.0f;
    const float2* tcls2 = reinterpret_cast<const float2*>(tcls + (size_t)cellbase * 20);
    if (cib == CPB) {
        int cell = tid / 10;
        int r = tid - cell * 10;          // cls f2 index within cell (0..9)
        #pragma unroll
        for (int k = 0; k < 10; k++) {
            int i = tid + k * TPB;        // == cell*10 + r
            float2 t = tcls2[i];
            float2 v = *reinterpret_cast<const float2*>(&s_pred[cell * 30 + 10 + 2 * r]);
            float obj = s_obj[cell];
            float dx = v.x - t.x, dy = v.y - t.y;
            acc_cls += obj * (dx * dx + dy * dy);
            r += 6; cell += 25;
            if (r >= 10) { r -= 10; ++cell; }   // 256 = 25*10 + 6
        }
    } else {
        for (int i = tid; i < cib * 10; i += TPB) {
            int cell = i / 10;
            int r = i - cell * 10;
            float2 t = tcls2[i];
            float2 v = *reinterpret_cast<const float2*>(&s_pred[cell * 30 + 10 + 2 * r]);
            float obj = s_obj[cell];
            float dx = v.x - t.x, dy = v.y - t.y;
            acc_cls += obj * (dx * dx + dy * dy);
        }
    }

    // ---- Phase B: per-cell noobj squares + IoU/reg/conf from SMEM ----
    float acc_reg = 0.0f, acc_conf = 0.0f, acc_nobjcnt = 0.0f, acc_noobj = 0.0f;
    if (tid < cib) {
        float obj = s_obj[tid];
        acc_nobjcnt = obj;

        const float* bb = &s_pred[tid * 30];
        float b1x = bb[0], b1y = bb[1], b1w = bb[2], b1h = bb[3], b1c = bb[4];
        float b2x = bb[5], b2y = bb[6], b2w = bb[7], b2h = bb[8], b2c = bb[9];

        float sq = b1x * b1x + b1y * b1y + b1w * b1w + b1h * b1h + b1c * b1c
                 + b2x * b2x + b2y * b2y + b2w * b2w + b2h * b2h + b2c * b2c;
        acc_noobj = (1.0f - obj) * sq;

        if (obj > 0.0f) {
            const float invS = 1.0f / 14.0f;
            float tcx = tb.x * invS, tcy = tb.y * invS;
            float tx1 = tcx - 0.5f * tb.z, ty1 = tcy - 0.5f * tb.w;
            float tx2 = tcx + 0.5f * tb.z, ty2 = tcy + 0.5f * tb.w;
            float tarea = (tx2 - tx1) * (ty2 - ty1);

            float iou1 = iou_pred_vs_tgt(b1x, b1y, b1w, b1h, tx1, ty1, tx2, ty2, tarea);
            float iou2 = iou_pred_vs_tgt(b2x, b2y, b2w, b2h, tx1, ty1, tx2, ty2, tarea);

            bool take1 = (iou1 >= iou2);
            float bx = take1 ? b1x : b2x;
            float by = take1 ? b1y : b2y;
            float bw = take1 ? b1w : b2w;
            float bh = take1 ? b1h : b2h;
            float bc = take1 ? b1c : b2c;
            float biou = take1 ? iou1 : iou2;

            float dx = bx - tb.x;
            float dy = by - tb.y;
            float dw = sqrtf(bw) - sqrtf(tb.z);
            float dh = sqrtf(bh) - sqrtf(tb.w);
            acc_reg = dx * dx + dy * dy + dw * dw + dh * dh;

            float dc = bc - biou;
            acc_conf = dc * dc;
        }
    }

    // ---- Block reduction of 5 accumulators -> SoA partials ----
    float vals[5] = {acc_nobjcnt, acc_reg, acc_conf, acc_noobj, acc_cls};
    #pragma unroll
    for (int k = 0; k < 5; k++) {
        float v = vals[k];
        #pragma unroll
        for (int off = 16; off > 0; off >>= 1)
            v += __shfl_down_sync(0xffffffffu, v, off);
        if (lane == 0) s_red[k * (TPB / 32) + warp] = v;
    }
    __syncthreads();
    if (tid < 5) {
        float v = 0.0f;
        #pragma unroll
        for (int w2 = 0; w2 < TPB / 32; w2++)
            v += s_red[tid * (TPB / 32) + w2];
        g_partials[tid * grid + bid] = v;
    }

    // ---- Last-block finalize ----
    if (tid == 0) {
        __threadfence();
        unsigned int old = atomicInc(&g_counter, (unsigned int)(grid - 1));
        s_last = (old == (unsigned int)(grid - 1)) ? 1 : 0;
    }
    __syncthreads();
    if (!s_last) return;

    volatile float* gp = g_partials;
    double acc[5] = {0.0, 0.0, 0.0, 0.0, 0.0};
    for (int i = tid; i < grid; i += TPB) {
        #pragma unroll
        for (int k = 0; k < 5; k++)
            acc[k] += (double)gp[k * grid + i];
    }
    #pragma unroll
    for (int k = 0; k < 5; k++) {
        double v = acc[k];
        #pragma unroll
        for (int off = 16; off > 0; off >>= 1)
            v += __shfl_down_sync(0xffffffffu, v, off);
        if (lane == 0) s_dred[warp] = v;
        __syncthreads();
        if (tid == 0) {
            double t = 0.0;
            #pragma unroll
            for (int w2 = 0; w2 < TPB / 32; w2++) t += s_dred[w2];
            s_tot[k] = t;
        }
        __syncthreads();
    }

    if (tid == 0) {
        double n_obj   = s_tot[0];
        double n_noobj = (double)n_cells - n_obj;
        double reg_loss   = 5.0 * s_tot[1] / n_obj;
        double conf_loss  = s_tot[2] / n_obj;
        double noobj_loss = 0.5 * s_tot[3] / n_noobj;
        double cls_loss   = s_tot[4] / (double)n_batch;
        double total = reg_loss + conf_loss + noobj_loss + cls_loss;
        out[0] = (float)total;
        out[1] = (float)reg_loss;
        out[2] = (float)conf_loss;
        out[3] = (float)noobj_loss;
        out[4] = (float)cls_loss;
    }
}

extern "C" void kernel_launch(void* const* d_in, const int* in_sizes, int n_in,
                              void* d_out, int out_size)
{
    const float* pred = (const float*)d_in[0];
    const float* tbox = (const float*)d_in[1];
    const float* tcls = (const float*)d_in[2];
    const void*  objmap = d_in[3];
    float* out = (float*)d_out;

    const int n_cells = in_sizes[3];                  // N * S * S
    const int n_batch = in_sizes[0] / (14 * 14 * 30);
    int grid = (n_cells + CPB - 1) / CPB;
    if (grid > MAX_GRID) grid = MAX_GRID;             // not reachable at this shape

    yolo_fused_kernel<<<grid, TPB>>>(pred, tbox, tcls, objmap,
                                     n_cells, (float)n_batch, out);
}